// round 2
// baseline (speedup 1.0000x reference)
#include <cuda_runtime.h>
#include <cuda_bf16.h>
#include <math_constants.h>

// Problem constants (fixed by the dataset)
#define NN   50000
#define EE   800000
#define E2   (EE + NN)      // edges + self loops = 850000
#define FIN  512
#define H1   8
#define C1   32
#define D1   (H1 * C1)      // 256
#define CLS  40

// ---------------- scratch (static device globals; no runtime alloc) ----------
__device__ float g_h1[NN * D1];          // layer1 linear output [N,256]
__device__ float g_as1[NN * H1];         // alpha_src layer1 [N,8]
__device__ float g_ad1[NN * H1];         // alpha_dst layer1 [N,8]
__device__ float g_hout1[NN * D1];       // elu(agg1 + b1) [N,256]
__device__ float g_h2lin[NN * CLS];      // layer2 linear output [N,40]
__device__ float g_as2[NN];
__device__ float g_ad2[NN];
__device__ float g_wbuf[E2 * H1];        // per-edge exp(logit) layer1
__device__ float g_wbuf2[E2];            // per-edge exp(logit) layer2
__device__ int   g_deg[NN];
__device__ int   g_incl[NN];
__device__ int   g_starts[NN];
__device__ int   g_cursor[NN];
__device__ int   g_ssrc[E2];             // src node per edge, sorted by dst
__device__ int   g_parts[64];
__device__ int   g_parts_ex[64];

// ---------------- SGEMM1: g_h1 = x @ W1   (M=50000, K=512, N=256) ------------
__global__ void sgemm1_kernel(const float* __restrict__ A, const float* __restrict__ B) {
    const int M = NN, N = D1, K = FIN;
    __shared__ float As[8][128];
    __shared__ float Bs[8][128];
    int t = threadIdx.x;                 // 256 threads
    int tx = t & 15, ty = t >> 4;
    int rowBase = blockIdx.y * 128;
    int colBase = blockIdx.x * 128;

    float acc[8][8];
#pragma unroll
    for (int i = 0; i < 8; i++)
#pragma unroll
        for (int j = 0; j < 8; j++) acc[i][j] = 0.f;

    int arow = t >> 1;
    int akq  = (t & 1) * 4;
    int brow = t >> 5;
    int bcol = (t & 31) * 4;
    int grow = rowBase + arow;

    for (int k0 = 0; k0 < K; k0 += 8) {
        float4 av = (grow < M) ? *(const float4*)&A[(size_t)grow * K + k0 + akq]
                               : make_float4(0.f, 0.f, 0.f, 0.f);
        As[akq + 0][arow] = av.x;
        As[akq + 1][arow] = av.y;
        As[akq + 2][arow] = av.z;
        As[akq + 3][arow] = av.w;
        float4 bv = *(const float4*)&B[(size_t)(k0 + brow) * N + colBase + bcol];
        *(float4*)&Bs[brow][bcol] = bv;
        __syncthreads();
#pragma unroll
        for (int kk = 0; kk < 8; kk++) {
            float a[8], b[8];
            float4 a0 = *(float4*)&As[kk][ty * 8];
            float4 a1 = *(float4*)&As[kk][ty * 8 + 4];
            float4 b0 = *(float4*)&Bs[kk][tx * 8];
            float4 b1 = *(float4*)&Bs[kk][tx * 8 + 4];
            a[0]=a0.x; a[1]=a0.y; a[2]=a0.z; a[3]=a0.w;
            a[4]=a1.x; a[5]=a1.y; a[6]=a1.z; a[7]=a1.w;
            b[0]=b0.x; b[1]=b0.y; b[2]=b0.z; b[3]=b0.w;
            b[4]=b1.x; b[5]=b1.y; b[6]=b1.z; b[7]=b1.w;
#pragma unroll
            for (int i = 0; i < 8; i++)
#pragma unroll
                for (int j = 0; j < 8; j++) acc[i][j] = fmaf(a[i], b[j], acc[i][j]);
        }
        __syncthreads();
    }
#pragma unroll
    for (int i = 0; i < 8; i++) {
        int row = rowBase + ty * 8 + i;
        if (row < M) {
            float4 v0 = make_float4(acc[i][0], acc[i][1], acc[i][2], acc[i][3]);
            float4 v1 = make_float4(acc[i][4], acc[i][5], acc[i][6], acc[i][7]);
            *(float4*)&g_h1[(size_t)row * N + colBase + tx * 8]     = v0;
            *(float4*)&g_h1[(size_t)row * N + colBase + tx * 8 + 4] = v1;
        }
    }
}

// ---------------- alpha1: per-node attention logits (warp per node) ----------
__global__ void alpha1_kernel(const float* __restrict__ a_src, const float* __restrict__ a_dst) {
    int gw = (blockIdx.x * blockDim.x + threadIdx.x) >> 5;
    int lane = threadIdx.x & 31;
    if (gw >= NN) return;
    const float* hp = &g_h1[(size_t)gw * D1];
#pragma unroll
    for (int h = 0; h < H1; h++) {
        float v = hp[h * 32 + lane];
        float s1 = v * __ldg(&a_src[h * 32 + lane]);
        float s2 = v * __ldg(&a_dst[h * 32 + lane]);
#pragma unroll
        for (int off = 16; off > 0; off >>= 1) {
            s1 += __shfl_xor_sync(0xffffffffu, s1, off);
            s2 += __shfl_xor_sync(0xffffffffu, s2, off);
        }
        if (lane == 0) {
            g_as1[gw * H1 + h] = s1;
            g_ad1[gw * H1 + h] = s2;
        }
    }
}

// ---------------- CSR build ---------------------------------------------------
__global__ void zero_deg_kernel() {
    int i = blockIdx.x * blockDim.x + threadIdx.x;
    if (i < NN) g_deg[i] = 0;
}

__global__ void hist_kernel(const int* __restrict__ ei) {
    int i = blockIdx.x * blockDim.x + threadIdx.x;
    if (i >= E2) return;
    int d = (i < EE) ? __ldg(&ei[EE + i]) : (i - EE);
    atomicAdd(&g_deg[d], 1);
}

__global__ void scan_block_kernel() {
    __shared__ int sh[1024];
    int tid = threadIdx.x;
    int i = blockIdx.x * 1024 + tid;
    int v = (i < NN) ? g_deg[i] : 0;
    sh[tid] = v;
    __syncthreads();
#pragma unroll
    for (int off = 1; off < 1024; off <<= 1) {
        int t = (tid >= off) ? sh[tid - off] : 0;
        __syncthreads();
        sh[tid] += t;
        __syncthreads();
    }
    if (i < NN) g_incl[i] = sh[tid];
    if (tid == 1023) g_parts[blockIdx.x] = sh[tid];
}

__global__ void scan_parts_kernel(int nb) {
    __shared__ int sh[64];
    int tid = threadIdx.x;
    int v = (tid < nb) ? g_parts[tid] : 0;
    sh[tid] = v;
    __syncthreads();
#pragma unroll
    for (int off = 1; off < 64; off <<= 1) {
        int t = (tid >= off) ? sh[tid - off] : 0;
        __syncthreads();
        sh[tid] += t;
        __syncthreads();
    }
    if (tid < nb) g_parts_ex[tid] = sh[tid] - v;
}

__global__ void finalize_scan_kernel() {
    int i = blockIdx.x * blockDim.x + threadIdx.x;
    if (i >= NN) return;
    int start = g_incl[i] - g_deg[i] + g_parts_ex[i >> 10];
    g_starts[i] = start;
    g_cursor[i] = start;
}

__global__ void fill_kernel(const int* __restrict__ ei) {
    int i = blockIdx.x * blockDim.x + threadIdx.x;
    if (i >= E2) return;
    int s, d;
    if (i < EE) { s = __ldg(&ei[i]); d = __ldg(&ei[EE + i]); }
    else        { s = i - EE; d = s; }
    int p = atomicAdd(&g_cursor[d], 1);
    g_ssrc[p] = s;
}

// ---------------- layer1 aggregation (warp per dst node) ----------------------
__global__ void agg1_kernel(const float* __restrict__ b1) {
    int n = (blockIdx.x * blockDim.x + threadIdx.x) >> 5;
    int lane = threadIdx.x & 31;
    if (n >= NN) return;
    int st = g_starts[n];
    int d  = g_deg[n];

    float adh[H1];
#pragma unroll
    for (int h = 0; h < H1; h++) adh[h] = g_ad1[n * H1 + h];

    // pass A: per-edge exp(leaky_relu(logit)) for all heads + denominator
    float den[H1];
#pragma unroll
    for (int h = 0; h < H1; h++) den[h] = 0.f;
    for (int j = lane; j < d; j += 32) {
        int s = __ldg(&g_ssrc[st + j]);
        float* wp = &g_wbuf[(size_t)(st + j) * H1];
        const float* asp = &g_as1[s * H1];
#pragma unroll
        for (int h = 0; h < H1; h++) {
            float e = __ldg(&asp[h]) + adh[h];
            e = fmaxf(e, 0.2f * e);          // leaky_relu(0.2)
            float ex = __expf(e);            // softmax shift-invariant; |e| small
            wp[h] = ex;
            den[h] += ex;
        }
    }
#pragma unroll
    for (int h = 0; h < H1; h++) {
#pragma unroll
        for (int off = 16; off > 0; off >>= 1)
            den[h] += __shfl_xor_sync(0xffffffffu, den[h], off);
    }
    float inv[H1];
#pragma unroll
    for (int h = 0; h < H1; h++) inv[h] = 1.f / (den[h] + 1e-16f);

    // pass B: weighted gather accumulate (whole warp per edge, lane = channel)
    float acc[H1];
#pragma unroll
    for (int h = 0; h < H1; h++) acc[h] = 0.f;
#pragma unroll 4
    for (int j = 0; j < d; j++) {
        int s = __ldg(&g_ssrc[st + j]);
        const float* wp = &g_wbuf[(size_t)(st + j) * H1];
        const float* hp = &g_h1[(size_t)s * D1];
#pragma unroll
        for (int h = 0; h < H1; h++) {
            float w = wp[h] * inv[h];
            acc[h] = fmaf(__ldg(&hp[h * 32 + lane]), w, acc[h]);
        }
    }

    // epilogue: +bias, ELU, store
#pragma unroll
    for (int h = 0; h < H1; h++) {
        float v = acc[h] + __ldg(&b1[h * 32 + lane]);
        v = (v > 0.f) ? v : expm1f(v);
        g_hout1[(size_t)n * D1 + h * 32 + lane] = v;
    }
}

// ---------------- layer2 linear + alpha2 (warp per node, W2 in smem) ----------
__global__ void layer2_linear_kernel(const float* __restrict__ W2,
                                     const float* __restrict__ a_src2,
                                     const float* __restrict__ a_dst2) {
    __shared__ float Ws[D1 * CLS + 64];
    __shared__ float as_sh[CLS], ad_sh[CLS];
    int tid = threadIdx.x;
    for (int i = tid; i < D1 * CLS + 64; i += blockDim.x)
        Ws[i] = (i < D1 * CLS) ? W2[i] : 0.f;
    if (tid < CLS) { as_sh[tid] = a_src2[tid]; ad_sh[tid] = a_dst2[tid]; }
    __syncthreads();

    int lane = tid & 31;
    int warpsPerBlock = blockDim.x >> 5;
    int gw = blockIdx.x * warpsPerBlock + (tid >> 5);
    int stride = gridDim.x * warpsPerBlock;

    for (int n = gw; n < NN; n += stride) {
        const float* xp = &g_hout1[(size_t)n * D1];
        float acc0a = 0.f, acc0b = 0.f, acc1a = 0.f, acc1b = 0.f;
#pragma unroll
        for (int kb = 0; kb < D1 / 32; kb++) {
            float xv = xp[kb * 32 + lane];
#pragma unroll
            for (int j = 0; j < 32; j += 2) {
                float xj0 = __shfl_sync(0xffffffffu, xv, j);
                float xj1 = __shfl_sync(0xffffffffu, xv, j + 1);
                int k0 = kb * 32 + j;
                acc0a = fmaf(xj0, Ws[k0 * CLS + lane], acc0a);
                acc1a = fmaf(xj0, Ws[k0 * CLS + 32 + lane], acc1a);
                acc0b = fmaf(xj1, Ws[(k0 + 1) * CLS + lane], acc0b);
                acc1b = fmaf(xj1, Ws[(k0 + 1) * CLS + 32 + lane], acc1b);
            }
        }
        float v0 = acc0a + acc0b;
        float v1 = acc1a + acc1b;
        g_h2lin[(size_t)n * CLS + lane] = v0;
        if (lane < CLS - 32) g_h2lin[(size_t)n * CLS + 32 + lane] = v1;
        float ps = v0 * as_sh[lane] + ((lane < CLS - 32) ? v1 * as_sh[32 + lane] : 0.f);
        float pd = v0 * ad_sh[lane] + ((lane < CLS - 32) ? v1 * ad_sh[32 + lane] : 0.f);
#pragma unroll
        for (int off = 16; off > 0; off >>= 1) {
            ps += __shfl_xor_sync(0xffffffffu, ps, off);
            pd += __shfl_xor_sync(0xffffffffu, pd, off);
        }
        if (lane == 0) { g_as2[n] = ps; g_ad2[n] = pd; }
    }
}

// ---------------- layer2 aggregation + log_softmax (warp per dst node) --------
__global__ void agg2_kernel(const float* __restrict__ b2, float* __restrict__ out) {
    int n = (blockIdx.x * blockDim.x + threadIdx.x) >> 5;
    int lane = threadIdx.x & 31;
    if (n >= NN) return;
    int st = g_starts[n];
    int d  = g_deg[n];
    float adn = g_ad2[n];

    float den = 0.f;
    for (int j = lane; j < d; j += 32) {
        int s = __ldg(&g_ssrc[st + j]);
        float e = __ldg(&g_as2[s]) + adn;
        e = fmaxf(e, 0.2f * e);
        float ex = __expf(e);
        g_wbuf2[st + j] = ex;
        den += ex;
    }
#pragma unroll
    for (int off = 16; off > 0; off >>= 1)
        den += __shfl_xor_sync(0xffffffffu, den, off);
    float inv = 1.f / (den + 1e-16f);

    float acc0 = 0.f, acc1 = 0.f;
#pragma unroll 4
    for (int j = 0; j < d; j++) {
        int s = __ldg(&g_ssrc[st + j]);
        float w = g_wbuf2[st + j] * inv;
        const float* hp = &g_h2lin[(size_t)s * CLS];
        acc0 = fmaf(__ldg(&hp[lane]), w, acc0);
        if (lane < CLS - 32) acc1 = fmaf(__ldg(&hp[32 + lane]), w, acc1);
    }
    float v0 = acc0 + __ldg(&b2[lane]);
    float v1 = (lane < CLS - 32) ? (acc1 + __ldg(&b2[32 + lane])) : -CUDART_INF_F;

    // log_softmax over 40 values held across the warp
    float m = fmaxf(v0, v1);
#pragma unroll
    for (int off = 16; off > 0; off >>= 1)
        m = fmaxf(m, __shfl_xor_sync(0xffffffffu, m, off));
    float s0 = __expf(v0 - m) + ((lane < CLS - 32) ? __expf(v1 - m) : 0.f);
#pragma unroll
    for (int off = 16; off > 0; off >>= 1)
        s0 += __shfl_xor_sync(0xffffffffu, s0, off);
    float lse = m + logf(s0);

    out[(size_t)n * CLS + lane] = v0 - lse;
    if (lane < CLS - 32) out[(size_t)n * CLS + 32 + lane] = v1 - lse;
}

// ---------------- launch ------------------------------------------------------
extern "C" void kernel_launch(void* const* d_in, const int* in_sizes, int n_in,
                              void* d_out, int out_size) {
    const float* x      = (const float*)d_in[0];
    const int*   ei     = (const int*)d_in[1];
    const float* W1     = (const float*)d_in[2];
    const float* a_src1 = (const float*)d_in[3];
    const float* a_dst1 = (const float*)d_in[4];
    const float* b1     = (const float*)d_in[5];
    const float* W2     = (const float*)d_in[6];
    const float* a_src2 = (const float*)d_in[7];
    const float* a_dst2 = (const float*)d_in[8];
    const float* b2     = (const float*)d_in[9];
    float* out = (float*)d_out;

    const int nb_scan = (NN + 1023) / 1024;   // 49

    // CSR build chain (independent of GEMM1 until agg1)
    zero_deg_kernel<<<(NN + 255) / 256, 256>>>();
    hist_kernel<<<(E2 + 255) / 256, 256>>>(ei);
    scan_block_kernel<<<nb_scan, 1024>>>();
    scan_parts_kernel<<<1, 64>>>(nb_scan);
    finalize_scan_kernel<<<(NN + 255) / 256, 256>>>();
    fill_kernel<<<(E2 + 255) / 256, 256>>>(ei);

    // layer 1
    sgemm1_kernel<<<dim3(2, (NN + 127) / 128), 256>>>(x, W1);
    alpha1_kernel<<<(NN * 32 + 255) / 256, 256>>>(a_src1, a_dst1);
    agg1_kernel<<<(NN * 32 + 255) / 256, 256>>>(b1);

    // layer 2
    layer2_linear_kernel<<<592, 256>>>(W2, a_src2, a_dst2);
    agg2_kernel<<<(NN * 32 + 255) / 256, 256>>>(b2, out);
}

// round 3
// speedup vs baseline: 1.2016x; 1.2016x over previous
#include <cuda_runtime.h>
#include <cuda_bf16.h>
#include <math_constants.h>
#include <cstdint>

// Problem constants (fixed by the dataset)
#define NN   50000
#define EE   800000
#define E2   (EE + NN)      // edges + self loops = 850000
#define FIN  512
#define H1   8
#define C1   32
#define D1   (H1 * C1)      // 256
#define CLS  40

// ---------------- scratch (static device globals; no runtime alloc) ----------
__device__ float g_h1[NN * D1];          // layer1 linear output [N,256]
__device__ float g_as1[NN * H1];
__device__ float g_ad1[NN * H1];
__device__ float g_hout1[NN * D1];       // elu(agg1 + b1) [N,256]
__device__ float g_h2lin[NN * CLS];
__device__ float g_as2[NN];
__device__ float g_ad2[NN];
__device__ float g_wbuf[E2 * H1];
__device__ float g_wbuf2[E2];
__device__ int   g_deg[NN];
__device__ int   g_incl[NN];
__device__ int   g_starts[NN];
__device__ int   g_cursor[NN];
__device__ int   g_ssrc[E2];
__device__ int   g_parts[64];
__device__ int   g_parts_ex[64];
// bf16 split-precision operands for GEMM1
__device__ uint32_t g_xhi[NN * (FIN / 2)];      // bf16 pairs (k even low, k odd high)
__device__ uint32_t g_xlo[NN * (FIN / 2)];
__device__ uint32_t g_w1t_hi[D1 * (FIN / 2)];   // W1 transposed: [n][kp]
__device__ uint32_t g_w1t_lo[D1 * (FIN / 2)];

// ---------------- bf16 split helpers -----------------------------------------
__device__ __forceinline__ void split2(float x, float y, uint32_t& hi, uint32_t& lo) {
    __nv_bfloat16 hx = __float2bfloat16_rn(x);
    __nv_bfloat16 hy = __float2bfloat16_rn(y);
    float lxf = x - __bfloat162float(hx);
    float lyf = y - __bfloat162float(hy);
    __nv_bfloat162 hv; hv.x = hx; hv.y = hy;
    __nv_bfloat162 lv = __floats2bfloat162_rn(lxf, lyf);
    hi = *reinterpret_cast<uint32_t*>(&hv);
    lo = *reinterpret_cast<uint32_t*>(&lv);
}

// ---------------- prep: split x into bf16 hi/lo pairs -------------------------
__global__ void prep_x_kernel(const float* __restrict__ x) {
    int i = blockIdx.x * blockDim.x + threadIdx.x;          // float4 index
    const int NQ = NN * FIN / 4;                            // 6,400,000
    if (i >= NQ) return;
    float4 v = ((const float4*)x)[i];
    uint32_t h0, l0, h1, l1;
    split2(v.x, v.y, h0, l0);
    split2(v.z, v.w, h1, l1);
    g_xhi[2 * i]     = h0;  g_xhi[2 * i + 1] = h1;
    g_xlo[2 * i]     = l0;  g_xlo[2 * i + 1] = l1;
}

// ---------------- prep: W1 -> transposed packed bf16 hi/lo --------------------
__global__ void prep_w_kernel(const float* __restrict__ W1) {
    int idx = blockIdx.x * blockDim.x + threadIdx.x;        // n*256 + kp
    if (idx >= D1 * (FIN / 2)) return;
    int n = idx >> 8;            // 0..255
    int kp = idx & 255;          // 0..255
    float a = W1[(size_t)(2 * kp) * D1 + n];
    float b = W1[(size_t)(2 * kp + 1) * D1 + n];
    uint32_t hi, lo;
    split2(a, b, hi, lo);
    g_w1t_hi[idx] = hi;
    g_w1t_lo[idx] = lo;
}

// ---------------- tensor-core GEMM1: g_h1 = x @ W1 ---------------------------
// block tile 128x128, 8 warps (4 M x 2 N), warp tile 32x64, K-stage 16
#define MMA_BF16(c, a0, a1, a2, a3, b0, b1)                                    \
    asm volatile(                                                              \
        "mma.sync.aligned.m16n8k16.row.col.f32.bf16.bf16.f32 "                 \
        "{%0,%1,%2,%3}, {%4,%5,%6,%7}, {%8,%9}, {%0,%1,%2,%3};\n"              \
        : "+f"(c[0]), "+f"(c[1]), "+f"(c[2]), "+f"(c[3])                       \
        : "r"(a0), "r"(a1), "r"(a2), "r"(a3), "r"(b0), "r"(b1))

__global__ void __launch_bounds__(256, 1) sgemm1_tc_kernel() {
    __shared__ uint32_t As_hi[2][128 * 8];
    __shared__ uint32_t As_lo[2][128 * 8];
    __shared__ uint32_t Bs_hi[2][128 * 8];
    __shared__ uint32_t Bs_lo[2][128 * 8];

    const int t = threadIdx.x, lane = t & 31, wid = t >> 5;
    const int warpM = wid >> 1, warpN = wid & 1;
    const int rowBase = blockIdx.y * 128, colBase = blockIdx.x * 128;

    // global load mapping: thread covers one row-half (4 uint32 = 8 k) per array
    const int lrow  = t >> 1;        // 0..127
    const int lhalf = t & 1;         // 0/1
    const int arow_g = rowBase + lrow;
    const bool avalid = arow_g < NN;
    const size_t a_base = (size_t)arow_g * (FIN / 2) + lhalf * 4;
    const size_t b_base = (size_t)(colBase + lrow) * (FIN / 2) + lhalf * 4;
    // swizzled smem write offset (uint32 units)
    const int s_off = lrow * 8 + ((lhalf * 4) ^ (lrow & 4));

    float acc[2][8][4];
#pragma unroll
    for (int mt = 0; mt < 2; mt++)
#pragma unroll
        for (int nt = 0; nt < 8; nt++)
#pragma unroll
            for (int q = 0; q < 4; q++) acc[mt][nt][q] = 0.f;

    const uint4 z4 = make_uint4(0, 0, 0, 0);
    uint4 ra_h, ra_l, rb_h, rb_l;

    // prologue: stage 0
    ra_h = avalid ? *(const uint4*)&g_xhi[a_base] : z4;
    ra_l = avalid ? *(const uint4*)&g_xlo[a_base] : z4;
    rb_h = *(const uint4*)&g_w1t_hi[b_base];
    rb_l = *(const uint4*)&g_w1t_lo[b_base];
    *(uint4*)&As_hi[0][s_off] = ra_h;
    *(uint4*)&As_lo[0][s_off] = ra_l;
    *(uint4*)&Bs_hi[0][s_off] = rb_h;
    *(uint4*)&Bs_lo[0][s_off] = rb_l;
    __syncthreads();

    const int NSTAGE = FIN / 16;    // 32
    for (int ks = 0; ks < NSTAGE; ks++) {
        const int cur = ks & 1;
        if (ks + 1 < NSTAGE) {
            size_t off = (size_t)(ks + 1) * 8;
            ra_h = avalid ? *(const uint4*)&g_xhi[a_base + off] : z4;
            ra_l = avalid ? *(const uint4*)&g_xlo[a_base + off] : z4;
            rb_h = *(const uint4*)&g_w1t_hi[b_base + off];
            rb_l = *(const uint4*)&g_w1t_lo[b_base + off];
        }

        // A fragments for both m-tiles
        uint32_t afh[2][4], afl[2][4];
#pragma unroll
        for (int mt = 0; mt < 2; mt++) {
            const int r  = warpM * 32 + mt * 16 + (lane >> 2);
            const int r8 = r + 8;
            const int kpa = lane & 3;
            afh[mt][0] = As_hi[cur][r  * 8 + (kpa       ^ (r  & 4))];
            afh[mt][1] = As_hi[cur][r8 * 8 + (kpa       ^ (r8 & 4))];
            afh[mt][2] = As_hi[cur][r  * 8 + ((kpa + 4) ^ (r  & 4))];
            afh[mt][3] = As_hi[cur][r8 * 8 + ((kpa + 4) ^ (r8 & 4))];
            afl[mt][0] = As_lo[cur][r  * 8 + (kpa       ^ (r  & 4))];
            afl[mt][1] = As_lo[cur][r8 * 8 + (kpa       ^ (r8 & 4))];
            afl[mt][2] = As_lo[cur][r  * 8 + ((kpa + 4) ^ (r  & 4))];
            afl[mt][3] = As_lo[cur][r8 * 8 + ((kpa + 4) ^ (r8 & 4))];
        }
#pragma unroll
        for (int nt = 0; nt < 8; nt++) {
            const int c = warpN * 64 + nt * 8 + (lane >> 2);
            const int kpb = lane & 3;
            const uint32_t bh0 = Bs_hi[cur][c * 8 + (kpb       ^ (c & 4))];
            const uint32_t bh1 = Bs_hi[cur][c * 8 + ((kpb + 4) ^ (c & 4))];
            const uint32_t bl0 = Bs_lo[cur][c * 8 + (kpb       ^ (c & 4))];
            const uint32_t bl1 = Bs_lo[cur][c * 8 + ((kpb + 4) ^ (c & 4))];
#pragma unroll
            for (int mt = 0; mt < 2; mt++) {
                MMA_BF16(acc[mt][nt], afh[mt][0], afh[mt][1], afh[mt][2], afh[mt][3], bh0, bh1);
                MMA_BF16(acc[mt][nt], afh[mt][0], afh[mt][1], afh[mt][2], afh[mt][3], bl0, bl1);
                MMA_BF16(acc[mt][nt], afl[mt][0], afl[mt][1], afl[mt][2], afl[mt][3], bh0, bh1);
            }
        }
        if (ks + 1 < NSTAGE) {
            const int nxt = 1 - cur;
            *(uint4*)&As_hi[nxt][s_off] = ra_h;
            *(uint4*)&As_lo[nxt][s_off] = ra_l;
            *(uint4*)&Bs_hi[nxt][s_off] = rb_h;
            *(uint4*)&Bs_lo[nxt][s_off] = rb_l;
            __syncthreads();
        }
    }

    // epilogue
#pragma unroll
    for (int mt = 0; mt < 2; mt++) {
        const int r = rowBase + warpM * 32 + mt * 16 + (lane >> 2);
#pragma unroll
        for (int nt = 0; nt < 8; nt++) {
            const int c = colBase + warpN * 64 + nt * 8 + (lane & 3) * 2;
            if (r < NN) {
                float2 v = make_float2(acc[mt][nt][0], acc[mt][nt][1]);
                *(float2*)&g_h1[(size_t)r * D1 + c] = v;
            }
            if (r + 8 < NN) {
                float2 v = make_float2(acc[mt][nt][2], acc[mt][nt][3]);
                *(float2*)&g_h1[(size_t)(r + 8) * D1 + c] = v;
            }
        }
    }
}

// ---------------- alpha1: per-node attention logits (warp per node) ----------
__global__ void alpha1_kernel(const float* __restrict__ a_src, const float* __restrict__ a_dst) {
    int gw = (blockIdx.x * blockDim.x + threadIdx.x) >> 5;
    int lane = threadIdx.x & 31;
    if (gw >= NN) return;
    const float* hp = &g_h1[(size_t)gw * D1];
#pragma unroll
    for (int h = 0; h < H1; h++) {
        float v = hp[h * 32 + lane];
        float s1 = v * __ldg(&a_src[h * 32 + lane]);
        float s2 = v * __ldg(&a_dst[h * 32 + lane]);
#pragma unroll
        for (int off = 16; off > 0; off >>= 1) {
            s1 += __shfl_xor_sync(0xffffffffu, s1, off);
            s2 += __shfl_xor_sync(0xffffffffu, s2, off);
        }
        if (lane == 0) {
            g_as1[gw * H1 + h] = s1;
            g_ad1[gw * H1 + h] = s2;
        }
    }
}

// ---------------- CSR build ---------------------------------------------------
__global__ void zero_deg_kernel() {
    int i = blockIdx.x * blockDim.x + threadIdx.x;
    if (i < NN) g_deg[i] = 0;
}

__global__ void hist_kernel(const int* __restrict__ ei) {
    int i = blockIdx.x * blockDim.x + threadIdx.x;
    if (i >= E2) return;
    int d = (i < EE) ? __ldg(&ei[EE + i]) : (i - EE);
    atomicAdd(&g_deg[d], 1);
}

__global__ void scan_block_kernel() {
    __shared__ int sh[1024];
    int tid = threadIdx.x;
    int i = blockIdx.x * 1024 + tid;
    int v = (i < NN) ? g_deg[i] : 0;
    sh[tid] = v;
    __syncthreads();
#pragma unroll
    for (int off = 1; off < 1024; off <<= 1) {
        int t = (tid >= off) ? sh[tid - off] : 0;
        __syncthreads();
        sh[tid] += t;
        __syncthreads();
    }
    if (i < NN) g_incl[i] = sh[tid];
    if (tid == 1023) g_parts[blockIdx.x] = sh[tid];
}

__global__ void scan_parts_kernel(int nb) {
    __shared__ int sh[64];
    int tid = threadIdx.x;
    int v = (tid < nb) ? g_parts[tid] : 0;
    sh[tid] = v;
    __syncthreads();
#pragma unroll
    for (int off = 1; off < 64; off <<= 1) {
        int t = (tid >= off) ? sh[tid - off] : 0;
        __syncthreads();
        sh[tid] += t;
        __syncthreads();
    }
    if (tid < nb) g_parts_ex[tid] = sh[tid] - v;
}

__global__ void finalize_scan_kernel() {
    int i = blockIdx.x * blockDim.x + threadIdx.x;
    if (i >= NN) return;
    int start = g_incl[i] - g_deg[i] + g_parts_ex[i >> 10];
    g_starts[i] = start;
    g_cursor[i] = start;
}

__global__ void fill_kernel(const int* __restrict__ ei) {
    int i = blockIdx.x * blockDim.x + threadIdx.x;
    if (i >= E2) return;
    int s, d;
    if (i < EE) { s = __ldg(&ei[i]); d = __ldg(&ei[EE + i]); }
    else        { s = i - EE; d = s; }
    int p = atomicAdd(&g_cursor[d], 1);
    g_ssrc[p] = s;
}

// ---------------- layer1 aggregation (warp per dst node) ----------------------
__global__ void agg1_kernel(const float* __restrict__ b1) {
    int n = (blockIdx.x * blockDim.x + threadIdx.x) >> 5;
    int lane = threadIdx.x & 31;
    if (n >= NN) return;
    int st = g_starts[n];
    int d  = g_deg[n];

    float adh[H1];
#pragma unroll
    for (int h = 0; h < H1; h++) adh[h] = g_ad1[n * H1 + h];

    float den[H1];
#pragma unroll
    for (int h = 0; h < H1; h++) den[h] = 0.f;
    for (int j = lane; j < d; j += 32) {
        int s = __ldg(&g_ssrc[st + j]);
        float* wp = &g_wbuf[(size_t)(st + j) * H1];
        const float* asp = &g_as1[s * H1];
#pragma unroll
        for (int h = 0; h < H1; h++) {
            float e = __ldg(&asp[h]) + adh[h];
            e = fmaxf(e, 0.2f * e);
            float ex = __expf(e);
            wp[h] = ex;
            den[h] += ex;
        }
    }
#pragma unroll
    for (int h = 0; h < H1; h++) {
#pragma unroll
        for (int off = 16; off > 0; off >>= 1)
            den[h] += __shfl_xor_sync(0xffffffffu, den[h], off);
    }
    float inv[H1];
#pragma unroll
    for (int h = 0; h < H1; h++) inv[h] = 1.f / (den[h] + 1e-16f);

    float acc[H1];
#pragma unroll
    for (int h = 0; h < H1; h++) acc[h] = 0.f;
#pragma unroll 4
    for (int j = 0; j < d; j++) {
        int s = __ldg(&g_ssrc[st + j]);
        const float* wp = &g_wbuf[(size_t)(st + j) * H1];
        const float* hp = &g_h1[(size_t)s * D1];
#pragma unroll
        for (int h = 0; h < H1; h++) {
            float w = wp[h] * inv[h];
            acc[h] = fmaf(__ldg(&hp[h * 32 + lane]), w, acc[h]);
        }
    }

#pragma unroll
    for (int h = 0; h < H1; h++) {
        float v = acc[h] + __ldg(&b1[h * 32 + lane]);
        v = (v > 0.f) ? v : expm1f(v);
        g_hout1[(size_t)n * D1 + h * 32 + lane] = v;
    }
}

// ---------------- layer2 linear + alpha2 (warp per node, W2 in smem) ----------
__global__ void layer2_linear_kernel(const float* __restrict__ W2,
                                     const float* __restrict__ a_src2,
                                     const float* __restrict__ a_dst2) {
    __shared__ float Ws[D1 * CLS + 64];
    __shared__ float as_sh[CLS], ad_sh[CLS];
    int tid = threadIdx.x;
    for (int i = tid; i < D1 * CLS + 64; i += blockDim.x)
        Ws[i] = (i < D1 * CLS) ? W2[i] : 0.f;
    if (tid < CLS) { as_sh[tid] = a_src2[tid]; ad_sh[tid] = a_dst2[tid]; }
    __syncthreads();

    int lane = tid & 31;
    int warpsPerBlock = blockDim.x >> 5;
    int gw = blockIdx.x * warpsPerBlock + (tid >> 5);
    int stride = gridDim.x * warpsPerBlock;

    for (int n = gw; n < NN; n += stride) {
        const float* xp = &g_hout1[(size_t)n * D1];
        float acc0a = 0.f, acc0b = 0.f, acc1a = 0.f, acc1b = 0.f;
#pragma unroll
        for (int kb = 0; kb < D1 / 32; kb++) {
            float xv = xp[kb * 32 + lane];
#pragma unroll
            for (int j = 0; j < 32; j += 2) {
                float xj0 = __shfl_sync(0xffffffffu, xv, j);
                float xj1 = __shfl_sync(0xffffffffu, xv, j + 1);
                int k0 = kb * 32 + j;
                acc0a = fmaf(xj0, Ws[k0 * CLS + lane], acc0a);
                acc1a = fmaf(xj0, Ws[k0 * CLS + 32 + lane], acc1a);
                acc0b = fmaf(xj1, Ws[(k0 + 1) * CLS + lane], acc0b);
                acc1b = fmaf(xj1, Ws[(k0 + 1) * CLS + 32 + lane], acc1b);
            }
        }
        float v0 = acc0a + acc0b;
        float v1 = acc1a + acc1b;
        g_h2lin[(size_t)n * CLS + lane] = v0;
        if (lane < CLS - 32) g_h2lin[(size_t)n * CLS + 32 + lane] = v1;
        float ps = v0 * as_sh[lane] + ((lane < CLS - 32) ? v1 * as_sh[32 + lane] : 0.f);
        float pd = v0 * ad_sh[lane] + ((lane < CLS - 32) ? v1 * ad_sh[32 + lane] : 0.f);
#pragma unroll
        for (int off = 16; off > 0; off >>= 1) {
            ps += __shfl_xor_sync(0xffffffffu, ps, off);
            pd += __shfl_xor_sync(0xffffffffu, pd, off);
        }
        if (lane == 0) { g_as2[n] = ps; g_ad2[n] = pd; }
    }
}

// ---------------- layer2 aggregation + log_softmax (warp per dst node) --------
__global__ void agg2_kernel(const float* __restrict__ b2, float* __restrict__ out) {
    int n = (blockIdx.x * blockDim.x + threadIdx.x) >> 5;
    int lane = threadIdx.x & 31;
    if (n >= NN) return;
    int st = g_starts[n];
    int d  = g_deg[n];
    float adn = g_ad2[n];

    float den = 0.f;
    for (int j = lane; j < d; j += 32) {
        int s = __ldg(&g_ssrc[st + j]);
        float e = __ldg(&g_as2[s]) + adn;
        e = fmaxf(e, 0.2f * e);
        float ex = __expf(e);
        g_wbuf2[st + j] = ex;
        den += ex;
    }
#pragma unroll
    for (int off = 16; off > 0; off >>= 1)
        den += __shfl_xor_sync(0xffffffffu, den, off);
    float inv = 1.f / (den + 1e-16f);

    float acc0 = 0.f, acc1 = 0.f;
#pragma unroll 4
    for (int j = 0; j < d; j++) {
        int s = __ldg(&g_ssrc[st + j]);
        float w = g_wbuf2[st + j] * inv;
        const float* hp = &g_h2lin[(size_t)s * CLS];
        acc0 = fmaf(__ldg(&hp[lane]), w, acc0);
        if (lane < CLS - 32) acc1 = fmaf(__ldg(&hp[32 + lane]), w, acc1);
    }
    float v0 = acc0 + __ldg(&b2[lane]);
    float v1 = (lane < CLS - 32) ? (acc1 + __ldg(&b2[32 + lane])) : -CUDART_INF_F;

    float m = fmaxf(v0, v1);
#pragma unroll
    for (int off = 16; off > 0; off >>= 1)
        m = fmaxf(m, __shfl_xor_sync(0xffffffffu, m, off));
    float s0 = __expf(v0 - m) + ((lane < CLS - 32) ? __expf(v1 - m) : 0.f);
#pragma unroll
    for (int off = 16; off > 0; off >>= 1)
        s0 += __shfl_xor_sync(0xffffffffu, s0, off);
    float lse = m + logf(s0);

    out[(size_t)n * CLS + lane] = v0 - lse;
    if (lane < CLS - 32) out[(size_t)n * CLS + 32 + lane] = v1 - lse;
}

// ---------------- launch ------------------------------------------------------
extern "C" void kernel_launch(void* const* d_in, const int* in_sizes, int n_in,
                              void* d_out, int out_size) {
    const float* x      = (const float*)d_in[0];
    const int*   ei     = (const int*)d_in[1];
    const float* W1     = (const float*)d_in[2];
    const float* a_src1 = (const float*)d_in[3];
    const float* a_dst1 = (const float*)d_in[4];
    const float* b1     = (const float*)d_in[5];
    const float* W2     = (const float*)d_in[6];
    const float* a_src2 = (const float*)d_in[7];
    const float* a_dst2 = (const float*)d_in[8];
    const float* b2     = (const float*)d_in[9];
    float* out = (float*)d_out;

    const int nb_scan = (NN + 1023) / 1024;   // 49

    // prep (1,2), then GEMM early (position for ncu capture window)
    prep_x_kernel<<<(NN * FIN / 4 + 255) / 256, 256>>>(x);
    prep_w_kernel<<<(D1 * (FIN / 2) + 255) / 256, 256>>>(W1);
    zero_deg_kernel<<<(NN + 255) / 256, 256>>>();
    sgemm1_tc_kernel<<<dim3(2, (NN + 127) / 128), 256>>>();

    // CSR build chain
    hist_kernel<<<(E2 + 255) / 256, 256>>>(ei);
    scan_block_kernel<<<nb_scan, 1024>>>();
    scan_parts_kernel<<<1, 64>>>(nb_scan);
    finalize_scan_kernel<<<(NN + 255) / 256, 256>>>();
    fill_kernel<<<(E2 + 255) / 256, 256>>>(ei);

    // layer 1
    alpha1_kernel<<<(NN * 32 + 255) / 256, 256>>>(a_src1, a_dst1);
    agg1_kernel<<<(NN * 32 + 255) / 256, 256>>>(b1);

    // layer 2
    layer2_linear_kernel<<<592, 256>>>(W2, a_src2, a_dst2);
    agg2_kernel<<<(NN * 32 + 255) / 256, 256>>>(b2, out);
}

// round 5
// speedup vs baseline: 1.2587x; 1.0475x over previous
#include <cuda_runtime.h>
#include <cuda_bf16.h>
#include <math_constants.h>
#include <cstdint>

// Problem constants (fixed by the dataset)
#define NN   50000
#define EE   800000
#define E2   (EE + NN)      // edges + self loops = 850000
#define FIN  512
#define H1   8
#define C1   32
#define D1   (H1 * C1)      // 256
#define CLS  40

// ---------------- scratch (static device globals; no runtime alloc) ----------
__device__ float g_h1[NN * D1];          // layer1 linear output [N,256]
__device__ float g_as1[NN * H1];
__device__ float g_ad1[NN * H1];
__device__ float g_hout1[NN * D1];       // elu(agg1 + b1) [N,256]
__device__ float g_h2lin[NN * CLS];
__device__ float g_as2[NN];
__device__ float g_ad2[NN];
__device__ float g_wbuf[E2 * H1];
__device__ float g_wbuf2[E2];
__device__ int   g_deg[NN];
__device__ int   g_incl[NN];
__device__ int   g_starts[NN];
__device__ int   g_cursor[NN];
__device__ int   g_ssrc[E2];
__device__ int   g_parts[64];
__device__ int   g_parts_ex[64];
// bf16 split-precision operands for GEMM1
__device__ uint32_t g_xhi[NN * (FIN / 2)];      // bf16 pairs (k even low, k odd high)
__device__ uint32_t g_xlo[NN * (FIN / 2)];
__device__ uint32_t g_w1t_hi[D1 * (FIN / 2)];   // W1 transposed: [n][kp]
__device__ uint32_t g_w1t_lo[D1 * (FIN / 2)];

// ---------------- bf16 split helpers -----------------------------------------
__device__ __forceinline__ void split2(float x, float y, uint32_t& hi, uint32_t& lo) {
    __nv_bfloat16 hx = __float2bfloat16_rn(x);
    __nv_bfloat16 hy = __float2bfloat16_rn(y);
    float lxf = x - __bfloat162float(hx);
    float lyf = y - __bfloat162float(hy);
    __nv_bfloat162 hv; hv.x = hx; hv.y = hy;
    __nv_bfloat162 lv = __floats2bfloat162_rn(lxf, lyf);
    hi = *reinterpret_cast<uint32_t*>(&hv);
    lo = *reinterpret_cast<uint32_t*>(&lv);
}

// ---------------- prep: split x into bf16 hi/lo pairs -------------------------
__global__ void prep_x_kernel(const float* __restrict__ x) {
    int i = blockIdx.x * blockDim.x + threadIdx.x;          // float4 index
    const int NQ = NN * FIN / 4;
    if (i >= NQ) return;
    float4 v = ((const float4*)x)[i];
    uint32_t h0, l0, h1, l1;
    split2(v.x, v.y, h0, l0);
    split2(v.z, v.w, h1, l1);
    g_xhi[2 * i]     = h0;  g_xhi[2 * i + 1] = h1;
    g_xlo[2 * i]     = l0;  g_xlo[2 * i + 1] = l1;
}

// ---------------- prep: W1 -> transposed packed bf16 hi/lo --------------------
__global__ void prep_w_kernel(const float* __restrict__ W1) {
    int idx = blockIdx.x * blockDim.x + threadIdx.x;        // n*256 + kp
    if (idx >= D1 * (FIN / 2)) return;
    int n = idx >> 8;
    int kp = idx & 255;
    float a = W1[(size_t)(2 * kp) * D1 + n];
    float b = W1[(size_t)(2 * kp + 1) * D1 + n];
    uint32_t hi, lo;
    split2(a, b, hi, lo);
    g_w1t_hi[idx] = hi;
    g_w1t_lo[idx] = lo;
}

// ---------------- tensor-core GEMM1: g_h1 = x @ W1 ---------------------------
#define MMA_BF16(c, a0, a1, a2, a3, b0, b1)                                    \
    asm volatile(                                                              \
        "mma.sync.aligned.m16n8k16.row.col.f32.bf16.bf16.f32 "                 \
        "{%0,%1,%2,%3}, {%4,%5,%6,%7}, {%8,%9}, {%0,%1,%2,%3};\n"              \
        : "+f"(c[0]), "+f"(c[1]), "+f"(c[2]), "+f"(c[3])                       \
        : "r"(a0), "r"(a1), "r"(a2), "r"(a3), "r"(b0), "r"(b1))

__device__ __forceinline__ void ldm4(uint32_t* r, uint32_t saddr) {
    asm volatile("ldmatrix.sync.aligned.m8n8.x4.shared.b16 {%0,%1,%2,%3}, [%4];"
                 : "=r"(r[0]), "=r"(r[1]), "=r"(r[2]), "=r"(r[3]) : "r"(saddr));
}

__global__ void __launch_bounds__(256, 2) sgemm1_tc_kernel() {
    __shared__ uint32_t As_hi[2][128 * 8];
    __shared__ uint32_t As_lo[2][128 * 8];
    __shared__ uint32_t Bs_hi[2][128 * 8];
    __shared__ uint32_t Bs_lo[2][128 * 8];

    const int t = threadIdx.x, lane = t & 31, wid = t >> 5;
    const int warpM = wid >> 1, warpN = wid & 1;
    const int rowBase = blockIdx.y * 128, colBase = blockIdx.x * 128;

    // global load mapping: thread covers one row-half (4 uint32 = 8 k)
    const int lrow  = t >> 1;
    const int lhalf = t & 1;
    const int arow_g = rowBase + lrow;
    const bool avalid = arow_g < NN;
    const size_t a_base = (size_t)arow_g * (FIN / 2) + lhalf * 4;
    const size_t b_base = (size_t)(colBase + lrow) * (FIN / 2) + lhalf * 4;
    const int s_off = lrow * 8 + ((lhalf * 4) ^ (lrow & 4));   // swizzled write idx

    // ldmatrix per-lane byte offsets (within one array buffer)
    const int lr = lane & 15, kq = lane >> 4;
    uint32_t off_a[2], off_b[4];
#pragma unroll
    for (int mt = 0; mt < 2; mt++) {
        int r = warpM * 32 + mt * 16 + lr;
        off_a[mt] = (uint32_t)(r * 8 + ((kq * 4) ^ (r & 4))) * 4u;
    }
#pragma unroll
    for (int np = 0; np < 4; np++) {
        int r = warpN * 64 + np * 16 + lr;
        off_b[np] = (uint32_t)(r * 8 + ((kq * 4) ^ (r & 4))) * 4u;
    }
    uint32_t baseAh[2], baseAl[2], baseBh[2], baseBl[2];
#pragma unroll
    for (int b = 0; b < 2; b++) {
        baseAh[b] = (uint32_t)__cvta_generic_to_shared(&As_hi[b][0]);
        baseAl[b] = (uint32_t)__cvta_generic_to_shared(&As_lo[b][0]);
        baseBh[b] = (uint32_t)__cvta_generic_to_shared(&Bs_hi[b][0]);
        baseBl[b] = (uint32_t)__cvta_generic_to_shared(&Bs_lo[b][0]);
    }

    float acc[2][8][4];
#pragma unroll
    for (int mt = 0; mt < 2; mt++)
#pragma unroll
        for (int nt = 0; nt < 8; nt++)
#pragma unroll
            for (int q = 0; q < 4; q++) acc[mt][nt][q] = 0.f;

    const uint4 z4 = make_uint4(0, 0, 0, 0);
    uint4 ra_h, ra_l, rb_h, rb_l;

    ra_h = avalid ? __ldg((const uint4*)&g_xhi[a_base]) : z4;
    ra_l = avalid ? __ldg((const uint4*)&g_xlo[a_base]) : z4;
    rb_h = __ldg((const uint4*)&g_w1t_hi[b_base]);
    rb_l = __ldg((const uint4*)&g_w1t_lo[b_base]);
    *(uint4*)&As_hi[0][s_off] = ra_h;
    *(uint4*)&As_lo[0][s_off] = ra_l;
    *(uint4*)&Bs_hi[0][s_off] = rb_h;
    *(uint4*)&Bs_lo[0][s_off] = rb_l;
    __syncthreads();

    const int NSTAGE = FIN / 16;    // 32
    for (int ks = 0; ks < NSTAGE; ks++) {
        const int cur = ks & 1;
        if (ks + 1 < NSTAGE) {
            size_t off = (size_t)(ks + 1) * 8;
            ra_h = avalid ? __ldg((const uint4*)&g_xhi[a_base + off]) : z4;
            ra_l = avalid ? __ldg((const uint4*)&g_xlo[a_base + off]) : z4;
            rb_h = __ldg((const uint4*)&g_w1t_hi[b_base + off]);
            rb_l = __ldg((const uint4*)&g_w1t_lo[b_base + off]);
        }

        uint32_t afh[2][4], afl[2][4];
        ldm4(afh[0], baseAh[cur] + off_a[0]);
        ldm4(afh[1], baseAh[cur] + off_a[1]);
        ldm4(afl[0], baseAl[cur] + off_a[0]);
        ldm4(afl[1], baseAl[cur] + off_a[1]);

#pragma unroll
        for (int np = 0; np < 4; np++) {
            uint32_t bh[4], bl[4];
            ldm4(bh, baseBh[cur] + off_b[np]);
            ldm4(bl, baseBl[cur] + off_b[np]);
#pragma unroll
            for (int mt = 0; mt < 2; mt++) {
                MMA_BF16(acc[mt][2 * np],     afh[mt][0], afh[mt][1], afh[mt][2], afh[mt][3], bh[0], bh[2]);
                MMA_BF16(acc[mt][2 * np],     afh[mt][0], afh[mt][1], afh[mt][2], afh[mt][3], bl[0], bl[2]);
                MMA_BF16(acc[mt][2 * np],     afl[mt][0], afl[mt][1], afl[mt][2], afl[mt][3], bh[0], bh[2]);
                MMA_BF16(acc[mt][2 * np + 1], afh[mt][0], afh[mt][1], afh[mt][2], afh[mt][3], bh[1], bh[3]);
                MMA_BF16(acc[mt][2 * np + 1], afh[mt][0], afh[mt][1], afh[mt][2], afh[mt][3], bl[1], bl[3]);
                MMA_BF16(acc[mt][2 * np + 1], afl[mt][0], afl[mt][1], afl[mt][2], afl[mt][3], bh[1], bh[3]);
            }
        }
        if (ks + 1 < NSTAGE) {
            const int nxt = 1 - cur;
            *(uint4*)&As_hi[nxt][s_off] = ra_h;
            *(uint4*)&As_lo[nxt][s_off] = ra_l;
            *(uint4*)&Bs_hi[nxt][s_off] = rb_h;
            *(uint4*)&Bs_lo[nxt][s_off] = rb_l;
            __syncthreads();
        }
    }

#pragma unroll
    for (int mt = 0; mt < 2; mt++) {
        const int r = rowBase + warpM * 32 + mt * 16 + (lane >> 2);
#pragma unroll
        for (int nt = 0; nt < 8; nt++) {
            const int c = colBase + warpN * 64 + nt * 8 + (lane & 3) * 2;
            if (r < NN) {
                float2 v = make_float2(acc[mt][nt][0], acc[mt][nt][1]);
                *(float2*)&g_h1[(size_t)r * D1 + c] = v;
            }
            if (r + 8 < NN) {
                float2 v = make_float2(acc[mt][nt][2], acc[mt][nt][3]);
                *(float2*)&g_h1[(size_t)(r + 8) * D1 + c] = v;
            }
        }
    }
}

// ---------------- alpha1: per-node attention logits (warp per node) ----------
__global__ void alpha1_kernel(const float* __restrict__ a_src, const float* __restrict__ a_dst) {
    int gw = (blockIdx.x * blockDim.x + threadIdx.x) >> 5;
    int lane = threadIdx.x & 31;
    if (gw >= NN) return;
    const float* hp = &g_h1[(size_t)gw * D1];
#pragma unroll
    for (int h = 0; h < H1; h++) {
        float v = hp[h * 32 + lane];
        float s1 = v * __ldg(&a_src[h * 32 + lane]);
        float s2 = v * __ldg(&a_dst[h * 32 + lane]);
#pragma unroll
        for (int off = 16; off > 0; off >>= 1) {
            s1 += __shfl_xor_sync(0xffffffffu, s1, off);
            s2 += __shfl_xor_sync(0xffffffffu, s2, off);
        }
        if (lane == 0) {
            g_as1[gw * H1 + h] = s1;
            g_ad1[gw * H1 + h] = s2;
        }
    }
}

// ---------------- CSR build ---------------------------------------------------
__global__ void zero_deg_kernel() {
    int i = blockIdx.x * blockDim.x + threadIdx.x;
    if (i < NN) g_deg[i] = 0;
}

__global__ void hist_kernel(const int* __restrict__ ei) {
    int i = blockIdx.x * blockDim.x + threadIdx.x;
    if (i >= E2) return;
    int d = (i < EE) ? __ldg(&ei[EE + i]) : (i - EE);
    atomicAdd(&g_deg[d], 1);
}

__global__ void scan_block_kernel() {
    __shared__ int sh[1024];
    int tid = threadIdx.x;
    int i = blockIdx.x * 1024 + tid;
    int v = (i < NN) ? g_deg[i] : 0;
    sh[tid] = v;
    __syncthreads();
#pragma unroll
    for (int off = 1; off < 1024; off <<= 1) {
        int t = (tid >= off) ? sh[tid - off] : 0;
        __syncthreads();
        sh[tid] += t;
        __syncthreads();
    }
    if (i < NN) g_incl[i] = sh[tid];
    if (tid == 1023) g_parts[blockIdx.x] = sh[tid];
}

__global__ void scan_parts_kernel(int nb) {
    __shared__ int sh[64];
    int tid = threadIdx.x;
    int v = (tid < nb) ? g_parts[tid] : 0;
    sh[tid] = v;
    __syncthreads();
#pragma unroll
    for (int off = 1; off < 64; off <<= 1) {
        int t = (tid >= off) ? sh[tid - off] : 0;
        __syncthreads();
        sh[tid] += t;
        __syncthreads();
    }
    if (tid < nb) g_parts_ex[tid] = sh[tid] - v;
}

__global__ void finalize_scan_kernel() {
    int i = blockIdx.x * blockDim.x + threadIdx.x;
    if (i >= NN) return;
    int start = g_incl[i] - g_deg[i] + g_parts_ex[i >> 10];
    g_starts[i] = start;
    g_cursor[i] = start;
}

__global__ void fill_kernel(const int* __restrict__ ei) {
    int i = blockIdx.x * blockDim.x + threadIdx.x;
    if (i >= E2) return;
    int s, d;
    if (i < EE) { s = __ldg(&ei[i]); d = __ldg(&ei[EE + i]); }
    else        { s = i - EE; d = s; }
    int p = atomicAdd(&g_cursor[d], 1);
    g_ssrc[p] = s;
}

// ---------------- layer1 aggregation (warp per node*head-pair) ----------------
__global__ void agg1_kernel(const float* __restrict__ b1) {
    int gw = (blockIdx.x * blockDim.x + threadIdx.x) >> 5;
    int lane = threadIdx.x & 31;
    int n  = gw >> 2;                // node
    int hb = gw & 3;                 // head pair 0..3
    if (n >= NN) return;
    const int h0 = hb * 2;
    int st = g_starts[n];
    int d  = g_deg[n];

    float ad0 = g_ad1[n * H1 + h0];
    float ad1 = g_ad1[n * H1 + h0 + 1];

    // pass A: per-edge exp for this warp's 2 heads + denominators
    float den0 = 0.f, den1 = 0.f;
    for (int j = lane; j < d; j += 32) {
        int s = __ldg(&g_ssrc[st + j]);
        float e0 = __ldg(&g_as1[s * H1 + h0])     + ad0;
        float e1 = __ldg(&g_as1[s * H1 + h0 + 1]) + ad1;
        e0 = fmaxf(e0, 0.2f * e0);
        e1 = fmaxf(e1, 0.2f * e1);
        float x0 = __expf(e0), x1 = __expf(e1);
        *(float2*)&g_wbuf[(size_t)(st + j) * H1 + h0] = make_float2(x0, x1);
        den0 += x0; den1 += x1;
    }
#pragma unroll
    for (int off = 16; off > 0; off >>= 1) {
        den0 += __shfl_xor_sync(0xffffffffu, den0, off);
        den1 += __shfl_xor_sync(0xffffffffu, den1, off);
    }
    float inv0 = 1.f / (den0 + 1e-16f);
    float inv1 = 1.f / (den1 + 1e-16f);

    // pass B: weighted gather (2 channels/lane per edge)
    float a0 = 0.f, a1 = 0.f;
#pragma unroll 8
    for (int j = 0; j < d; j++) {
        int s = __ldg(&g_ssrc[st + j]);
        float2 w = *(const float2*)&g_wbuf[(size_t)(st + j) * H1 + h0];
        const float* hp = &g_h1[(size_t)s * D1 + h0 * 32];
        a0 = fmaf(__ldg(&hp[lane]),      w.x * inv0, a0);
        a1 = fmaf(__ldg(&hp[32 + lane]), w.y * inv1, a1);
    }

    float v0 = a0 + __ldg(&b1[h0 * 32 + lane]);
    float v1 = a1 + __ldg(&b1[(h0 + 1) * 32 + lane]);
    v0 = (v0 > 0.f) ? v0 : expm1f(v0);
    v1 = (v1 > 0.f) ? v1 : expm1f(v1);
    g_hout1[(size_t)n * D1 + h0 * 32 + lane]       = v0;
    g_hout1[(size_t)n * D1 + (h0 + 1) * 32 + lane] = v1;
}

// ---------------- layer2 linear + alpha2 (warp per node, W2 in smem) ----------
__global__ void layer2_linear_kernel(const float* __restrict__ W2,
                                     const float* __restrict__ a_src2,
                                     const float* __restrict__ a_dst2) {
    __shared__ float Ws[D1 * CLS + 64];
    __shared__ float as_sh[CLS], ad_sh[CLS];
    int tid = threadIdx.x;
    for (int i = tid; i < D1 * CLS + 64; i += blockDim.x)
        Ws[i] = (i < D1 * CLS) ? W2[i] : 0.f;
    if (tid < CLS) { as_sh[tid] = a_src2[tid]; ad_sh[tid] = a_dst2[tid]; }
    __syncthreads();

    int lane = tid & 31;
    int warpsPerBlock = blockDim.x >> 5;
    int gw = blockIdx.x * warpsPerBlock + (tid >> 5);
    int stride = gridDim.x * warpsPerBlock;

    for (int n = gw; n < NN; n += stride) {
        const float* xp = &g_hout1[(size_t)n * D1];
        float acc0a = 0.f, acc0b = 0.f, acc1a = 0.f, acc1b = 0.f;
#pragma unroll
        for (int kb = 0; kb < D1 / 32; kb++) {
            float xv = xp[kb * 32 + lane];
#pragma unroll
            for (int j = 0; j < 32; j += 2) {
                float xj0 = __shfl_sync(0xffffffffu, xv, j);
                float xj1 = __shfl_sync(0xffffffffu, xv, j + 1);
                int k0 = kb * 32 + j;
                acc0a = fmaf(xj0, Ws[k0 * CLS + lane], acc0a);
                acc1a = fmaf(xj0, Ws[k0 * CLS + 32 + lane], acc1a);
                acc0b = fmaf(xj1, Ws[(k0 + 1) * CLS + lane], acc0b);
                acc1b = fmaf(xj1, Ws[(k0 + 1) * CLS + 32 + lane], acc1b);
            }
        }
        float v0 = acc0a + acc0b;
        float v1 = acc1a + acc1b;
        g_h2lin[(size_t)n * CLS + lane] = v0;
        if (lane < CLS - 32) g_h2lin[(size_t)n * CLS + 32 + lane] = v1;
        float ps = v0 * as_sh[lane] + ((lane < CLS - 32) ? v1 * as_sh[32 + lane] : 0.f);
        float pd = v0 * ad_sh[lane] + ((lane < CLS - 32) ? v1 * ad_sh[32 + lane] : 0.f);
#pragma unroll
        for (int off = 16; off > 0; off >>= 1) {
            ps += __shfl_xor_sync(0xffffffffu, ps, off);
            pd += __shfl_xor_sync(0xffffffffu, pd, off);
        }
        if (lane == 0) { g_as2[n] = ps; g_ad2[n] = pd; }
    }
}

// ---------------- layer2 aggregation + log_softmax (warp per dst node) --------
__global__ void agg2_kernel(const float* __restrict__ b2, float* __restrict__ out) {
    int n = (blockIdx.x * blockDim.x + threadIdx.x) >> 5;
    int lane = threadIdx.x & 31;
    if (n >= NN) return;
    int st = g_starts[n];
    int d  = g_deg[n];
    float adn = g_ad2[n];

    float den = 0.f;
    for (int j = lane; j < d; j += 32) {
        int s = __ldg(&g_ssrc[st + j]);
        float e = __ldg(&g_as2[s]) + adn;
        e = fmaxf(e, 0.2f * e);
        float ex = __expf(e);
        g_wbuf2[st + j] = ex;
        den += ex;
    }
#pragma unroll
    for (int off = 16; off > 0; off >>= 1)
        den += __shfl_xor_sync(0xffffffffu, den, off);
    float inv = 1.f / (den + 1e-16f);

    float acc0 = 0.f, acc1 = 0.f;
#pragma unroll 4
    for (int j = 0; j < d; j++) {
        int s = __ldg(&g_ssrc[st + j]);
        float w = g_wbuf2[st + j] * inv;
        const float* hp = &g_h2lin[(size_t)s * CLS];
        acc0 = fmaf(__ldg(&hp[lane]), w, acc0);
        if (lane < CLS - 32) acc1 = fmaf(__ldg(&hp[32 + lane]), w, acc1);
    }
    float v0 = acc0 + __ldg(&b2[lane]);
    float v1 = (lane < CLS - 32) ? (acc1 + __ldg(&b2[32 + lane])) : -CUDART_INF_F;

    float m = fmaxf(v0, v1);
#pragma unroll
    for (int off = 16; off > 0; off >>= 1)
        m = fmaxf(m, __shfl_xor_sync(0xffffffffu, m, off));
    float s0 = __expf(v0 - m) + ((lane < CLS - 32) ? __expf(v1 - m) : 0.f);
#pragma unroll
    for (int off = 16; off > 0; off >>= 1)
        s0 += __shfl_xor_sync(0xffffffffu, s0, off);
    float lse = m + logf(s0);

    out[(size_t)n * CLS + lane] = v0 - lse;
    if (lane < CLS - 32) out[(size_t)n * CLS + 32 + lane] = v1 - lse;
}

// ---------------- launch ------------------------------------------------------
extern "C" void kernel_launch(void* const* d_in, const int* in_sizes, int n_in,
                              void* d_out, int out_size) {
    const float* x      = (const float*)d_in[0];
    const int*   ei     = (const int*)d_in[1];
    const float* W1     = (const float*)d_in[2];
    const float* a_src1 = (const float*)d_in[3];
    const float* a_dst1 = (const float*)d_in[4];
    const float* b1     = (const float*)d_in[5];
    const float* W2     = (const float*)d_in[6];
    const float* a_src2 = (const float*)d_in[7];
    const float* a_dst2 = (const float*)d_in[8];
    const float* b2     = (const float*)d_in[9];
    float* out = (float*)d_out;

    const int nb_scan = (NN + 1023) / 1024;   // 49

    // prep, then GEMM at launch slot 4 (ncu capture window)
    prep_x_kernel<<<(NN * FIN / 4 + 255) / 256, 256>>>(x);
    prep_w_kernel<<<(D1 * (FIN / 2) + 255) / 256, 256>>>(W1);
    zero_deg_kernel<<<(NN + 255) / 256, 256>>>();
    sgemm1_tc_kernel<<<dim3(2, (NN + 127) / 128), 256>>>();

    // CSR build chain
    hist_kernel<<<(E2 + 255) / 256, 256>>>(ei);
    scan_block_kernel<<<nb_scan, 1024>>>();
    scan_parts_kernel<<<1, 64>>>(nb_scan);
    finalize_scan_kernel<<<(NN + 255) / 256, 256>>>();
    fill_kernel<<<(E2 + 255) / 256, 256>>>(ei);

    // layer 1
    alpha1_kernel<<<(NN * 32 + 255) / 256, 256>>>(a_src1, a_dst1);
    agg1_kernel<<<((size_t)NN * 4 * 32 + 255) / 256, 256>>>(b1);

    // layer 2
    layer2_linear_kernel<<<592, 256>>>(W2, a_src2, a_dst2);
    agg2_kernel<<<(NN * 32 + 255) / 256, 256>>>(b2, out);
}